// round 1
// baseline (speedup 1.0000x reference)
#include <cuda_runtime.h>
#include <math.h>

#define Bb 4
#define Tt 4096
#define Cc 1024
#define Hh 64
#define BM 128      // queries per attention block
#define KT 64       // keys per inner tile
#define NSPLIT 8
#define SCALE 0.03125f   // C^-0.5 = 1/32

// ---- scratch (no cudaMalloc allowed) ----
__device__ float g_q[Bb*Tt*Hh];
__device__ float g_k[Bb*Tt*Hh];
__device__ float g_v[Bb*Tt*Hh];
__device__ float g_pm[Bb*Tt*NSPLIT];
__device__ float g_pl[Bb*Tt*NSPLIT];
__device__ float g_pacc[(size_t)Bb*Tt*NSPLIT*Hh];

// ============================================================
// Kernel 1: QKV projection.  [16384 x 1024] @ [1024 x 64]
// 64x64 output tile per block, K-step 16, 256 threads, 4x4 micro-tile.
// blockIdx.y selects which of Wq/Wk/Wv.
// ============================================================
__global__ __launch_bounds__(256) void proj_kernel(
    const float* __restrict__ x,
    const float* __restrict__ Wq,
    const float* __restrict__ Wk,
    const float* __restrict__ Wv)
{
    const float* W;
    float* out;
    if (blockIdx.y == 0)      { W = Wq; out = g_q; }
    else if (blockIdx.y == 1) { W = Wk; out = g_k; }
    else                      { W = Wv; out = g_v; }

    const int row0 = blockIdx.x * 64;
    __shared__ float As[16][64];   // [k][m]
    __shared__ float Bs[16][64];   // [k][n]

    const int tid = threadIdx.x;
    const int tx = tid & 15;       // n-quad
    const int ty = tid >> 4;       // m-quad

    float acc[4][4];
#pragma unroll
    for (int u = 0; u < 4; ++u)
#pragma unroll
        for (int w = 0; w < 4; ++w) acc[u][w] = 0.f;

    for (int k0 = 0; k0 < Cc; k0 += 16) {
        // load A tile: 64 rows x 16 k
#pragma unroll
        for (int r = 0; r < 4; ++r) {
            int li = tid + r * 256;
            int mm = li >> 4, kk = li & 15;
            As[kk][mm] = x[(size_t)(row0 + mm) * Cc + k0 + kk];
        }
        // load B tile: 16 k x 64 n  (coalesced)
#pragma unroll
        for (int r = 0; r < 4; ++r) {
            int li = tid + r * 256;
            int kk = li >> 6, nn = li & 63;
            Bs[kk][nn] = W[(size_t)(k0 + kk) * Hh + nn];
        }
        __syncthreads();
#pragma unroll
        for (int kk = 0; kk < 16; ++kk) {
            float4 a  = *reinterpret_cast<const float4*>(&As[kk][ty * 4]);
            float4 bb = *reinterpret_cast<const float4*>(&Bs[kk][tx * 4]);
            float av[4] = {a.x, a.y, a.z, a.w};
            float bv[4] = {bb.x, bb.y, bb.z, bb.w};
#pragma unroll
            for (int u = 0; u < 4; ++u)
#pragma unroll
                for (int w = 0; w < 4; ++w)
                    acc[u][w] = fmaf(av[u], bv[w], acc[u][w]);
        }
        __syncthreads();
    }
#pragma unroll
    for (int u = 0; u < 4; ++u) {
        float4 o = make_float4(acc[u][0], acc[u][1], acc[u][2], acc[u][3]);
        *reinterpret_cast<float4*>(&out[(size_t)(row0 + ty * 4 + u) * Hh + tx * 4]) = o;
    }
}

// ============================================================
// Kernel 2: attention partials with split-K over key range.
// grid: (T/BM, NSPLIT, B), block: 128 threads, 1 query row per thread.
// Online softmax over this split's key tiles; partial (m, l, acc[64]) out.
// ============================================================
__global__ __launch_bounds__(BM) void attn_partial_kernel()
{
    const int qt = (Tt / BM - 1) - blockIdx.x;   // big tiles first
    const int sp = blockIdx.y;
    const int b  = blockIdx.z;
    const int tid = threadIdx.x;
    const int i = qt * BM + tid;                 // query row within batch

    __shared__ float4 Ks4[KT * (Hh / 4)];        // [key][h4]  16KB
    __shared__ float4 Vs4[KT * (Hh / 4)];        // 16KB

    const int n_kt_total = (qt + 1) * (BM / KT);
    const int per = (n_kt_total + NSPLIT - 1) / NSPLIT;
    const int kt0 = sp * per;
    const int kt1 = min(kt0 + per, n_kt_total);

    // q in registers
    float4 q4[Hh / 4];
    {
        const float4* qg = reinterpret_cast<const float4*>(g_q + ((size_t)b * Tt + i) * Hh);
#pragma unroll
        for (int h4 = 0; h4 < Hh / 4; ++h4) q4[h4] = qg[h4];
    }

    float m = -1e30f, l = 0.f;
    float4 acc4[Hh / 4];
#pragma unroll
    for (int h4 = 0; h4 < Hh / 4; ++h4) acc4[h4] = make_float4(0.f, 0.f, 0.f, 0.f);

    for (int kt = kt0; kt < kt1; ++kt) {
        const int jb = kt * KT;
        {
            const float4* kg = reinterpret_cast<const float4*>(g_k + ((size_t)b * Tt + jb) * Hh);
            const float4* vg = reinterpret_cast<const float4*>(g_v + ((size_t)b * Tt + jb) * Hh);
#pragma unroll
            for (int r = 0; r < (KT * Hh / 4) / BM; ++r) {
                Ks4[tid + r * BM] = kg[tid + r * BM];
                Vs4[tid + r * BM] = vg[tid + r * BM];
            }
        }
        __syncthreads();

#pragma unroll
        for (int c = 0; c < KT / 16; ++c) {
            float s[16];
#pragma unroll
            for (int j = 0; j < 16; ++j) s[j] = 0.f;
#pragma unroll
            for (int h4 = 0; h4 < Hh / 4; ++h4) {
                float4 qv = q4[h4];
#pragma unroll
                for (int j = 0; j < 16; ++j) {
                    float4 kv = Ks4[(c * 16 + j) * (Hh / 4) + h4];
                    s[j] = fmaf(qv.x, kv.x, s[j]);
                    s[j] = fmaf(qv.y, kv.y, s[j]);
                    s[j] = fmaf(qv.z, kv.z, s[j]);
                    s[j] = fmaf(qv.w, kv.w, s[j]);
                }
            }
            // mask + scale + chunk max
            float cm = -1e30f;
#pragma unroll
            for (int j = 0; j < 16; ++j) {
                int key = jb + c * 16 + j;
                s[j] = (key <= i) ? s[j] * SCALE : -1e30f;
                cm = fmaxf(cm, s[j]);
            }
            float m_new = fmaxf(m, cm);
            float corr = __expf(m - m_new);
            l *= corr;
#pragma unroll
            for (int h4 = 0; h4 < Hh / 4; ++h4) {
                acc4[h4].x *= corr; acc4[h4].y *= corr;
                acc4[h4].z *= corr; acc4[h4].w *= corr;
            }
            m = m_new;
#pragma unroll
            for (int j = 0; j < 16; ++j) {
                float p = __expf(s[j] - m_new);
                l += p;
#pragma unroll
                for (int h4 = 0; h4 < Hh / 4; ++h4) {
                    float4 vv = Vs4[(c * 16 + j) * (Hh / 4) + h4];
                    acc4[h4].x = fmaf(p, vv.x, acc4[h4].x);
                    acc4[h4].y = fmaf(p, vv.y, acc4[h4].y);
                    acc4[h4].z = fmaf(p, vv.z, acc4[h4].z);
                    acc4[h4].w = fmaf(p, vv.w, acc4[h4].w);
                }
            }
        }
        __syncthreads();
    }

    const size_t pidx = ((size_t)b * Tt + i) * NSPLIT + sp;
    g_pm[pidx] = m;
    g_pl[pidx] = l;
    float4* pa = reinterpret_cast<float4*>(g_pacc) + pidx * (Hh / 4);
#pragma unroll
    for (int h4 = 0; h4 < Hh / 4; ++h4) pa[h4] = acc4[h4];
}

// ============================================================
// Kernel 3: merge splits (log-sum-exp combine) -> output.
// 2 queries per 128-thread block, 1 head-elem per thread.
// ============================================================
__global__ __launch_bounds__(128) void attn_reduce_kernel(float* __restrict__ out)
{
    const int tid = threadIdx.x;
    const size_t qq = (size_t)blockIdx.x * 2 + (tid >> 6);
    const int h = tid & 63;

    float m_tot = -1e30f;
#pragma unroll
    for (int s = 0; s < NSPLIT; ++s)
        m_tot = fmaxf(m_tot, g_pm[qq * NSPLIT + s]);

    float num = 0.f, den = 0.f;
#pragma unroll
    for (int s = 0; s < NSPLIT; ++s) {
        float w = __expf(g_pm[qq * NSPLIT + s] - m_tot);
        den += w * g_pl[qq * NSPLIT + s];
        num += w * g_pacc[(qq * NSPLIT + s) * Hh + h];
    }
    out[qq * Hh + h] = num / den;
}

// ============================================================
extern "C" void kernel_launch(void* const* d_in, const int* in_sizes, int n_in,
                              void* d_out, int out_size)
{
    const float* x  = (const float*)d_in[0];
    const float* Wq = (const float*)d_in[1];
    const float* Wk = (const float*)d_in[2];
    const float* Wv = (const float*)d_in[3];
    float* out = (float*)d_out;

    dim3 pgrid(Bb * Tt / 64, 3);
    proj_kernel<<<pgrid, 256>>>(x, Wq, Wk, Wv);

    dim3 agrid(Tt / BM, NSPLIT, Bb);
    attn_partial_kernel<<<agrid, BM>>>();

    attn_reduce_kernel<<<Bb * Tt / 2, 128>>>(out);
}

// round 3
// speedup vs baseline: 1.1966x; 1.1966x over previous
#include <cuda_runtime.h>
#include <math.h>
#include <stdint.h>

#define Bb 4
#define Tt 4096
#define Cc 1024
#define Hh 64
#define BM 128      // queries per attention block
#define KT 64       // keys per inner tile
#define NSPLIT 8
#define SCALE 0.03125f   // C^-0.5 = 1/32

// ---- scratch (no cudaMalloc allowed) ----
__device__ float g_q[Bb*Tt*Hh];
__device__ float g_k[Bb*Tt*Hh];
__device__ float g_v[Bb*Tt*Hh];
__device__ float g_pm[Bb*Tt*NSPLIT];
__device__ float g_pl[Bb*Tt*NSPLIT];
__device__ float g_pacc[(size_t)Bb*Tt*NSPLIT*Hh];

__device__ __forceinline__ float tf32r(float x) {  // round-to-nearest tf32
    uint32_t u;
    asm("cvt.rna.tf32.f32 %0, %1;" : "=r"(u) : "f"(x));
    return __uint_as_float(u);
}

__device__ __forceinline__ void mma_tf32(float* d, const uint32_t* a, uint32_t b0, uint32_t b1) {
    asm volatile(
        "mma.sync.aligned.m16n8k8.row.col.f32.tf32.tf32.f32 "
        "{%0,%1,%2,%3}, {%4,%5,%6,%7}, {%8,%9}, {%0,%1,%2,%3};"
        : "+f"(d[0]), "+f"(d[1]), "+f"(d[2]), "+f"(d[3])
        : "r"(a[0]), "r"(a[1]), "r"(a[2]), "r"(a[3]), "r"(b0), "r"(b1));
}

// ============================================================
// Kernel 1: QKV projection via mma.sync tf32 (hi/lo split on A).
// Block: 128 threads (4 warps). M-tile 64 (16 rows/warp), N=64, K-chunk 32.
// grid: (BT/64, 3).
// ============================================================
#define AS_STRIDE 36
#define BS_STRIDE 72

__global__ __launch_bounds__(128) void proj_mma_kernel(
    const float* __restrict__ x,
    const float* __restrict__ Wq,
    const float* __restrict__ Wk,
    const float* __restrict__ Wv)
{
    __shared__ float As_hi[64][AS_STRIDE];
    __shared__ float As_lo[64][AS_STRIDE];
    __shared__ float Bs[32][BS_STRIDE];

    const float* W;
    float* out;
    if (blockIdx.y == 0)      { W = Wq; out = g_q; }
    else if (blockIdx.y == 1) { W = Wk; out = g_k; }
    else                      { W = Wv; out = g_v; }

    const int row0 = blockIdx.x * 64;
    const int tid = threadIdx.x;
    const int wid = tid >> 5, lid = tid & 31;
    const int m0 = wid * 16;
    const int fr = lid >> 2;     // fragment row 0..7
    const int fc = lid & 3;      // fragment col 0..3

    float acc[8][4];
#pragma unroll
    for (int nt = 0; nt < 8; ++nt)
#pragma unroll
        for (int u = 0; u < 4; ++u) acc[nt][u] = 0.f;

    for (int kc = 0; kc < Cc / 32; ++kc) {
        const int k0c = kc * 32;
        // --- A tile: 64 rows x 32 k, hi/lo split ---
#pragma unroll
        for (int r = 0; r < 4; ++r) {
            int f = tid + r * 128;
            int m = f >> 3, c4 = f & 7;
            float4 a = *reinterpret_cast<const float4*>(x + (size_t)(row0 + m) * Cc + k0c + c4 * 4);
            float hx = tf32r(a.x), hy = tf32r(a.y), hz = tf32r(a.z), hw = tf32r(a.w);
            As_hi[m][c4 * 4 + 0] = hx;  As_lo[m][c4 * 4 + 0] = tf32r(a.x - hx);
            As_hi[m][c4 * 4 + 1] = hy;  As_lo[m][c4 * 4 + 1] = tf32r(a.y - hy);
            As_hi[m][c4 * 4 + 2] = hz;  As_lo[m][c4 * 4 + 2] = tf32r(a.z - hz);
            As_hi[m][c4 * 4 + 3] = hw;  As_lo[m][c4 * 4 + 3] = tf32r(a.w - hw);
        }
        // --- B tile: 32 k x 64 n ---
#pragma unroll
        for (int r = 0; r < 4; ++r) {
            int f = tid + r * 128;
            int kk = f >> 4, c4 = f & 15;
            float4 w4 = *reinterpret_cast<const float4*>(W + (size_t)(k0c + kk) * Hh + c4 * 4);
            Bs[kk][c4 * 4 + 0] = tf32r(w4.x);
            Bs[kk][c4 * 4 + 1] = tf32r(w4.y);
            Bs[kk][c4 * 4 + 2] = tf32r(w4.z);
            Bs[kk][c4 * 4 + 3] = tf32r(w4.w);
        }
        __syncthreads();

#pragma unroll
        for (int ks = 0; ks < 4; ++ks) {
            const int k0 = ks * 8;
            uint32_t ahi[4], alo[4];
            ahi[0] = __float_as_uint(As_hi[m0 + fr    ][k0 + fc    ]);
            ahi[1] = __float_as_uint(As_hi[m0 + fr + 8][k0 + fc    ]);
            ahi[2] = __float_as_uint(As_hi[m0 + fr    ][k0 + fc + 4]);
            ahi[3] = __float_as_uint(As_hi[m0 + fr + 8][k0 + fc + 4]);
            alo[0] = __float_as_uint(As_lo[m0 + fr    ][k0 + fc    ]);
            alo[1] = __float_as_uint(As_lo[m0 + fr + 8][k0 + fc    ]);
            alo[2] = __float_as_uint(As_lo[m0 + fr    ][k0 + fc + 4]);
            alo[3] = __float_as_uint(As_lo[m0 + fr + 8][k0 + fc + 4]);
#pragma unroll
            for (int nt = 0; nt < 8; ++nt) {
                uint32_t b0 = __float_as_uint(Bs[k0 + fc    ][nt * 8 + fr]);
                uint32_t b1 = __float_as_uint(Bs[k0 + fc + 4][nt * 8 + fr]);
                mma_tf32(acc[nt], ahi, b0, b1);
                mma_tf32(acc[nt], alo, b0, b1);
            }
        }
        __syncthreads();
    }

    // epilogue: C fragment (row fr (+8), col 2*fc (+1)) per n-tile
    float* obase = out + (size_t)(row0 + m0) * Hh;
#pragma unroll
    for (int nt = 0; nt < 8; ++nt) {
        int col = nt * 8 + 2 * fc;
        *reinterpret_cast<float2*>(obase + (size_t)fr * Hh + col)       = make_float2(acc[nt][0], acc[nt][1]);
        *reinterpret_cast<float2*>(obase + (size_t)(fr + 8) * Hh + col) = make_float2(acc[nt][2], acc[nt][3]);
    }
}

// ============================================================
// Kernel 2: attention partials with split-K over key range (unchanged).
// ============================================================
__global__ __launch_bounds__(BM) void attn_partial_kernel()
{
    const int qt = (Tt / BM - 1) - blockIdx.x;   // big tiles first
    const int sp = blockIdx.y;
    const int b  = blockIdx.z;
    const int tid = threadIdx.x;
    const int i = qt * BM + tid;                 // query row within batch

    __shared__ float4 Ks4[KT * (Hh / 4)];        // 16KB
    __shared__ float4 Vs4[KT * (Hh / 4)];        // 16KB

    const int n_kt_total = (qt + 1) * (BM / KT);
    const int per = (n_kt_total + NSPLIT - 1) / NSPLIT;
    const int kt0 = sp * per;
    const int kt1 = min(kt0 + per, n_kt_total);

    float4 q4[Hh / 4];
    {
        const float4* qg = reinterpret_cast<const float4*>(g_q + ((size_t)b * Tt + i) * Hh);
#pragma unroll
        for (int h4 = 0; h4 < Hh / 4; ++h4) q4[h4] = qg[h4];
    }

    float m = -1e30f, l = 0.f;
    float4 acc4[Hh / 4];
#pragma unroll
    for (int h4 = 0; h4 < Hh / 4; ++h4) acc4[h4] = make_float4(0.f, 0.f, 0.f, 0.f);

    for (int kt = kt0; kt < kt1; ++kt) {
        const int jb = kt * KT;
        {
            const float4* kg = reinterpret_cast<const float4*>(g_k + ((size_t)b * Tt + jb) * Hh);
            const float4* vg = reinterpret_cast<const float4*>(g_v + ((size_t)b * Tt + jb) * Hh);
#pragma unroll
            for (int r = 0; r < (KT * Hh / 4) / BM; ++r) {
                Ks4[tid + r * BM] = kg[tid + r * BM];
                Vs4[tid + r * BM] = vg[tid + r * BM];
            }
        }
        __syncthreads();

#pragma unroll
        for (int c = 0; c < KT / 16; ++c) {
            float s[16];
#pragma unroll
            for (int j = 0; j < 16; ++j) s[j] = 0.f;
#pragma unroll
            for (int h4 = 0; h4 < Hh / 4; ++h4) {
                float4 qv = q4[h4];
#pragma unroll
                for (int j = 0; j < 16; ++j) {
                    float4 kv = Ks4[(c * 16 + j) * (Hh / 4) + h4];
                    s[j] = fmaf(qv.x, kv.x, s[j]);
                    s[j] = fmaf(qv.y, kv.y, s[j]);
                    s[j] = fmaf(qv.z, kv.z, s[j]);
                    s[j] = fmaf(qv.w, kv.w, s[j]);
                }
            }
            float cm = -1e30f;
#pragma unroll
            for (int j = 0; j < 16; ++j) {
                int key = jb + c * 16 + j;
                s[j] = (key <= i) ? s[j] * SCALE : -1e30f;
                cm = fmaxf(cm, s[j]);
            }
            float m_new = fmaxf(m, cm);
            float corr = __expf(m - m_new);
            l *= corr;
#pragma unroll
            for (int h4 = 0; h4 < Hh / 4; ++h4) {
                acc4[h4].x *= corr; acc4[h4].y *= corr;
                acc4[h4].z *= corr; acc4[h4].w *= corr;
            }
            m = m_new;
#pragma unroll
            for (int j = 0; j < 16; ++j) {
                float p = __expf(s[j] - m_new);
                l += p;
#pragma unroll
                for (int h4 = 0; h4 < Hh / 4; ++h4) {
                    float4 vv = Vs4[(c * 16 + j) * (Hh / 4) + h4];
                    acc4[h4].x = fmaf(p, vv.x, acc4[h4].x);
                    acc4[h4].y = fmaf(p, vv.y, acc4[h4].y);
                    acc4[h4].z = fmaf(p, vv.z, acc4[h4].z);
                    acc4[h4].w = fmaf(p, vv.w, acc4[h4].w);
                }
            }
        }
        __syncthreads();
    }

    const size_t pidx = ((size_t)b * Tt + i) * NSPLIT + sp;
    g_pm[pidx] = m;
    g_pl[pidx] = l;
    float4* pa = reinterpret_cast<float4*>(g_pacc) + pidx * (Hh / 4);
#pragma unroll
    for (int h4 = 0; h4 < Hh / 4; ++h4) pa[h4] = acc4[h4];
}

// ============================================================
// Kernel 3: merge splits (unchanged).
// ============================================================
__global__ __launch_bounds__(128) void attn_reduce_kernel(float* __restrict__ out)
{
    const int tid = threadIdx.x;
    const size_t qq = (size_t)blockIdx.x * 2 + (tid >> 6);
    const int h = tid & 63;

    float m_tot = -1e30f;
#pragma unroll
    for (int s = 0; s < NSPLIT; ++s)
        m_tot = fmaxf(m_tot, g_pm[qq * NSPLIT + s]);

    float num = 0.f, den = 0.f;
#pragma unroll
    for (int s = 0; s < NSPLIT; ++s) {
        float w = __expf(g_pm[qq * NSPLIT + s] - m_tot);
        den += w * g_pl[qq * NSPLIT + s];
        num += w * g_pacc[(qq * NSPLIT + s) * Hh + h];
    }
    out[qq * Hh + h] = num / den;
}

// ============================================================
extern "C" void kernel_launch(void* const* d_in, const int* in_sizes, int n_in,
                              void* d_out, int out_size)
{
    const float* x  = (const float*)d_in[0];
    const float* Wq = (const float*)d_in[1];
    const float* Wk = (const float*)d_in[2];
    const float* Wv = (const float*)d_in[3];
    float* out = (float*)d_out;

    dim3 pgrid(Bb * Tt / 64, 3);
    proj_mma_kernel<<<pgrid, 128>>>(x, Wq, Wk, Wv);

    dim3 agrid(Tt / BM, NSPLIT, Bb);
    attn_partial_kernel<<<agrid, BM>>>();

    attn_reduce_kernel<<<Bb * Tt / 2, 128>>>(out);
}

// round 5
// speedup vs baseline: 3.6579x; 3.0570x over previous
#include <cuda_runtime.h>
#include <math.h>
#include <stdint.h>

#define Bb 4
#define Tt 4096
#define Cc 1024
#define Hh 64
#define BM 128      // queries per attention CTA
#define KT 32       // keys per inner tile
#define NSPLIT 8
#define SCALE 0.03125f   // C^-0.5 = 1/32

// ---- scratch (no cudaMalloc allowed) ----
__device__ float g_q[Bb*Tt*Hh];
__device__ float g_k[Bb*Tt*Hh];
__device__ float g_v[Bb*Tt*Hh];
__device__ float g_pm[Bb*Tt*NSPLIT];
__device__ float g_pl[Bb*Tt*NSPLIT];
__device__ float g_pacc[(size_t)Bb*Tt*NSPLIT*Hh];

__device__ __forceinline__ float tf32r(float x) {  // round-to-nearest tf32
    uint32_t u;
    asm("cvt.rna.tf32.f32 %0, %1;" : "=r"(u) : "f"(x));
    return __uint_as_float(u);
}

__device__ __forceinline__ void mma_tf32(float* d, const uint32_t* a, uint32_t b0, uint32_t b1) {
    asm volatile(
        "mma.sync.aligned.m16n8k8.row.col.f32.tf32.tf32.f32 "
        "{%0,%1,%2,%3}, {%4,%5,%6,%7}, {%8,%9}, {%0,%1,%2,%3};"
        : "+f"(d[0]), "+f"(d[1]), "+f"(d[2]), "+f"(d[3])
        : "r"(a[0]), "r"(a[1]), "r"(a[2]), "r"(a[3]), "r"(b0), "r"(b1));
}

// ============================================================
// Kernel 1: QKV projection via mma.sync tf32 (hi/lo split on A).
// ============================================================
#define AS_STRIDE 36
#define BS_STRIDE 72

__global__ __launch_bounds__(128) void proj_mma_kernel(
    const float* __restrict__ x,
    const float* __restrict__ Wq,
    const float* __restrict__ Wk,
    const float* __restrict__ Wv)
{
    __shared__ float As_hi[64][AS_STRIDE];
    __shared__ float As_lo[64][AS_STRIDE];
    __shared__ float Bs[32][BS_STRIDE];

    const float* W;
    float* out;
    if (blockIdx.y == 0)      { W = Wq; out = g_q; }
    else if (blockIdx.y == 1) { W = Wk; out = g_k; }
    else                      { W = Wv; out = g_v; }

    const int row0 = blockIdx.x * 64;
    const int tid = threadIdx.x;
    const int wid = tid >> 5, lid = tid & 31;
    const int m0 = wid * 16;
    const int fr = lid >> 2;     // fragment row 0..7
    const int fc = lid & 3;      // fragment col 0..3

    float acc[8][4];
#pragma unroll
    for (int nt = 0; nt < 8; ++nt)
#pragma unroll
        for (int u = 0; u < 4; ++u) acc[nt][u] = 0.f;

    for (int kc = 0; kc < Cc / 32; ++kc) {
        const int k0c = kc * 32;
#pragma unroll
        for (int r = 0; r < 4; ++r) {
            int f = tid + r * 128;
            int m = f >> 3, c4 = f & 7;
            float4 a = *reinterpret_cast<const float4*>(x + (size_t)(row0 + m) * Cc + k0c + c4 * 4);
            float hx = tf32r(a.x), hy = tf32r(a.y), hz = tf32r(a.z), hw = tf32r(a.w);
            As_hi[m][c4 * 4 + 0] = hx;  As_lo[m][c4 * 4 + 0] = tf32r(a.x - hx);
            As_hi[m][c4 * 4 + 1] = hy;  As_lo[m][c4 * 4 + 1] = tf32r(a.y - hy);
            As_hi[m][c4 * 4 + 2] = hz;  As_lo[m][c4 * 4 + 2] = tf32r(a.z - hz);
            As_hi[m][c4 * 4 + 3] = hw;  As_lo[m][c4 * 4 + 3] = tf32r(a.w - hw);
        }
#pragma unroll
        for (int r = 0; r < 4; ++r) {
            int f = tid + r * 128;
            int kk = f >> 4, c4 = f & 15;
            float4 w4 = *reinterpret_cast<const float4*>(W + (size_t)(k0c + kk) * Hh + c4 * 4);
            Bs[kk][c4 * 4 + 0] = tf32r(w4.x);
            Bs[kk][c4 * 4 + 1] = tf32r(w4.y);
            Bs[kk][c4 * 4 + 2] = tf32r(w4.z);
            Bs[kk][c4 * 4 + 3] = tf32r(w4.w);
        }
        __syncthreads();

#pragma unroll
        for (int ks = 0; ks < 4; ++ks) {
            const int k0 = ks * 8;
            uint32_t ahi[4], alo[4];
            ahi[0] = __float_as_uint(As_hi[m0 + fr    ][k0 + fc    ]);
            ahi[1] = __float_as_uint(As_hi[m0 + fr + 8][k0 + fc    ]);
            ahi[2] = __float_as_uint(As_hi[m0 + fr    ][k0 + fc + 4]);
            ahi[3] = __float_as_uint(As_hi[m0 + fr + 8][k0 + fc + 4]);
            alo[0] = __float_as_uint(As_lo[m0 + fr    ][k0 + fc    ]);
            alo[1] = __float_as_uint(As_lo[m0 + fr + 8][k0 + fc    ]);
            alo[2] = __float_as_uint(As_lo[m0 + fr    ][k0 + fc + 4]);
            alo[3] = __float_as_uint(As_lo[m0 + fr + 8][k0 + fc + 4]);
#pragma unroll
            for (int nt = 0; nt < 8; ++nt) {
                uint32_t b0 = __float_as_uint(Bs[k0 + fc    ][nt * 8 + fr]);
                uint32_t b1 = __float_as_uint(Bs[k0 + fc + 4][nt * 8 + fr]);
                mma_tf32(acc[nt], ahi, b0, b1);
                mma_tf32(acc[nt], alo, b0, b1);
            }
        }
        __syncthreads();
    }

    float* obase = out + (size_t)(row0 + m0) * Hh;
#pragma unroll
    for (int nt = 0; nt < 8; ++nt) {
        int col = nt * 8 + 2 * fc;
        *reinterpret_cast<float2*>(obase + (size_t)fr * Hh + col)       = make_float2(acc[nt][0], acc[nt][1]);
        *reinterpret_cast<float2*>(obase + (size_t)(fr + 8) * Hh + col) = make_float2(acc[nt][2], acc[nt][3]);
    }
}

// ============================================================
// Kernel 2: flash attention partials via mma.sync tf32.
// S^T = K @ Q^T  (A=K natural layout, B=Q frags in registers),
// softmax state per-column, P round-trip through smem, O = P@V.
// grid (T/BM, NSPLIT, B), 256 threads (8 warps, 16 q-rows each).
// ============================================================
#define PS_S 36
#define KS_S 68
#define VS_S 72

__global__ __launch_bounds__(256) void attn_mma_kernel()
{
    __shared__ float Ps[BM * PS_S];      // Q staging, then P tile
    __shared__ float Ks[KT * KS_S];
    __shared__ float Vs[KT * VS_S];
    __shared__ float s_corr[BM];

    const int qt = (Tt / BM - 1) - blockIdx.x;   // big tiles first
    const int sp = blockIdx.y;
    const int b  = blockIdx.z;
    const int q0 = qt * BM;
    const int tid = threadIdx.x, wid = tid >> 5, lid = tid & 31;
    const int fr = lid >> 2, fc = lid & 3;
    const int m0 = wid * 16;

    const int n_kt = (qt + 1) * (BM / KT);
    const int per = (n_kt + NSPLIT - 1) / NSPLIT;
    const int kt0 = sp * per;
    const int kt1 = min(kt0 + per, n_kt);

    if (kt0 >= kt1) {   // empty split: zero partials
        int q = tid >> 1, half = tid & 1;
        size_t pidx = ((size_t)b * Tt + q0 + q) * NSPLIT + sp;
        if (half == 0) { g_pm[pidx] = -1e30f; g_pl[pidx] = 0.f; }
        float4 z = make_float4(0.f, 0.f, 0.f, 0.f);
        float4* pa = reinterpret_cast<float4*>(g_pacc + pidx * Hh) + half * 8;
#pragma unroll
        for (int i2 = 0; i2 < 8; ++i2) pa[i2] = z;
        return;
    }

    // ---- stage Q, hoist B-fragments to registers (two h-halves) ----
    uint32_t qf[8][2][2];   // [k-step][n-subtile][b0/b1]
#pragma unroll
    for (int half = 0; half < 2; ++half) {
#pragma unroll
        for (int r = 0; r < 4; ++r) {
            int idx = tid + r * 256;
            int q = idx >> 3, h4 = idx & 7;
            float4 v = *reinterpret_cast<const float4*>(
                g_q + ((size_t)b * Tt + q0 + q) * Hh + half * 32 + h4 * 4);
            float* d = &Ps[q * PS_S + h4 * 4];
            d[0] = tf32r(v.x); d[1] = tf32r(v.y); d[2] = tf32r(v.z); d[3] = tf32r(v.w);
        }
        __syncthreads();
#pragma unroll
        for (int ks = 0; ks < 4; ++ks)
#pragma unroll
            for (int nt = 0; nt < 2; ++nt) {
                qf[half * 4 + ks][nt][0] = __float_as_uint(Ps[(m0 + 8 * nt + fr) * PS_S + ks * 8 + fc]);
                qf[half * 4 + ks][nt][1] = __float_as_uint(Ps[(m0 + 8 * nt + fr) * PS_S + ks * 8 + fc + 4]);
            }
        __syncthreads();
    }

    float o[8][4];
#pragma unroll
    for (int nt = 0; nt < 8; ++nt)
#pragma unroll
        for (int u = 0; u < 4; ++u) o[nt][u] = 0.f;
    float m_run[2][2], l_run[2][2];
#pragma unroll
    for (int a = 0; a < 2; ++a)
#pragma unroll
        for (int c = 0; c < 2; ++c) { m_run[a][c] = -1e30f; l_run[a][c] = 0.f; }

    for (int kt = kt0; kt < kt1; ++kt) {
        const int jb = kt * KT;
        // ---- load K, V tiles (tf32-rounded) ----
#pragma unroll
        for (int r = 0; r < 2; ++r) {
            int idx = tid + r * 256;
            int key = idx >> 4, h4 = idx & 15;
            size_t gidx = ((size_t)b * Tt + jb + key) * Hh + h4 * 4;
            float4 kv = *reinterpret_cast<const float4*>(g_k + gidx);
            float* dk = &Ks[key * KS_S + h4 * 4];
            dk[0] = tf32r(kv.x); dk[1] = tf32r(kv.y); dk[2] = tf32r(kv.z); dk[3] = tf32r(kv.w);
            float4 vv = *reinterpret_cast<const float4*>(g_v + gidx);
            float* dv = &Vs[key * VS_S + h4 * 4];
            dv[0] = tf32r(vv.x); dv[1] = tf32r(vv.y); dv[2] = tf32r(vv.z); dv[3] = tf32r(vv.w);
        }
        __syncthreads();

        // ---- S^T = K @ Q^T : [32 keys][16 q] per warp ----
        float sacc[2][2][4];
#pragma unroll
        for (int mt = 0; mt < 2; ++mt)
#pragma unroll
            for (int nt = 0; nt < 2; ++nt)
#pragma unroll
                for (int u = 0; u < 4; ++u) sacc[mt][nt][u] = 0.f;
#pragma unroll
        for (int ks = 0; ks < 8; ++ks) {
            uint32_t ak[2][4];
#pragma unroll
            for (int mt = 0; mt < 2; ++mt) {
                ak[mt][0] = __float_as_uint(Ks[(16 * mt + fr    ) * KS_S + ks * 8 + fc    ]);
                ak[mt][1] = __float_as_uint(Ks[(16 * mt + fr + 8) * KS_S + ks * 8 + fc    ]);
                ak[mt][2] = __float_as_uint(Ks[(16 * mt + fr    ) * KS_S + ks * 8 + fc + 4]);
                ak[mt][3] = __float_as_uint(Ks[(16 * mt + fr + 8) * KS_S + ks * 8 + fc + 4]);
            }
#pragma unroll
            for (int mt = 0; mt < 2; ++mt)
#pragma unroll
                for (int nt = 0; nt < 2; ++nt)
                    mma_tf32(sacc[mt][nt], ak[mt], qf[ks][nt][0], qf[ks][nt][1]);
        }

        // ---- per-column online softmax ----
#pragma unroll
        for (int nt = 0; nt < 2; ++nt)
#pragma unroll
        for (int cp = 0; cp < 2; ++cp) {
            const int qloc = m0 + 8 * nt + 2 * fc + cp;
            const int qg = q0 + qloc;
            float sv[4];
#pragma unroll
            for (int mt = 0; mt < 2; ++mt)
#pragma unroll
                for (int s2 = 0; s2 < 2; ++s2) {
                    int keyg = jb + 16 * mt + 8 * s2 + fr;
                    float v = sacc[mt][nt][s2 * 2 + cp] * SCALE;
                    sv[mt * 2 + s2] = (keyg <= qg) ? v : -1e30f;
                }
            float cm = fmaxf(fmaxf(sv[0], sv[1]), fmaxf(sv[2], sv[3]));
            cm = fmaxf(cm, __shfl_xor_sync(0xffffffffu, cm, 4));
            cm = fmaxf(cm, __shfl_xor_sync(0xffffffffu, cm, 8));
            cm = fmaxf(cm, __shfl_xor_sync(0xffffffffu, cm, 16));
            float mn = fmaxf(m_run[nt][cp], cm);
            float corr = __expf(m_run[nt][cp] - mn);
            m_run[nt][cp] = mn;
            float tl = 0.f;
#pragma unroll
            for (int u = 0; u < 4; ++u) { sv[u] = __expf(sv[u] - mn); tl += sv[u]; }
            tl += __shfl_xor_sync(0xffffffffu, tl, 4);
            tl += __shfl_xor_sync(0xffffffffu, tl, 8);
            tl += __shfl_xor_sync(0xffffffffu, tl, 16);
            l_run[nt][cp] = l_run[nt][cp] * corr + tl;
#pragma unroll
            for (int mt = 0; mt < 2; ++mt)
#pragma unroll
                for (int s2 = 0; s2 < 2; ++s2)
                    Ps[qloc * PS_S + 16 * mt + 8 * s2 + fr] = tf32r(sv[mt * 2 + s2]);
            if (fr == 0) s_corr[qloc] = corr;
        }
        __syncwarp();

        // ---- rescale O, then O += P @ V ----
        float clo = s_corr[m0 + fr], chi = s_corr[m0 + fr + 8];
#pragma unroll
        for (int nt = 0; nt < 8; ++nt) {
            o[nt][0] *= clo; o[nt][1] *= clo;
            o[nt][2] *= chi; o[nt][3] *= chi;
        }
#pragma unroll
        for (int ks = 0; ks < 4; ++ks) {
            uint32_t ap[4];
            ap[0] = __float_as_uint(Ps[(m0 + fr    ) * PS_S + ks * 8 + fc    ]);
            ap[1] = __float_as_uint(Ps[(m0 + fr + 8) * PS_S + ks * 8 + fc    ]);
            ap[2] = __float_as_uint(Ps[(m0 + fr    ) * PS_S + ks * 8 + fc + 4]);
            ap[3] = __float_as_uint(Ps[(m0 + fr + 8) * PS_S + ks * 8 + fc + 4]);
#pragma unroll
            for (int nt = 0; nt < 8; ++nt) {
                uint32_t b0 = __float_as_uint(Vs[(ks * 8 + fc    ) * VS_S + nt * 8 + fr]);
                uint32_t b1 = __float_as_uint(Vs[(ks * 8 + fc + 4) * VS_S + nt * 8 + fr]);
                mma_tf32(o[nt], ap, b0, b1);
            }
        }
        __syncthreads();
    }

    // ---- store partials ----
    if (fr == 0) {
#pragma unroll
        for (int nt = 0; nt < 2; ++nt)
#pragma unroll
            for (int cp = 0; cp < 2; ++cp) {
                int qloc = m0 + 8 * nt + 2 * fc + cp;
                size_t pidx = ((size_t)b * Tt + q0 + qloc) * NSPLIT + sp;
                g_pm[pidx] = m_run[nt][cp];
                g_pl[pidx] = l_run[nt][cp];
            }
    }
    {
        size_t p_lo = ((size_t)b * Tt + q0 + m0 + fr    ) * NSPLIT + sp;
        size_t p_hi = ((size_t)b * Tt + q0 + m0 + fr + 8) * NSPLIT + sp;
        float* alo = g_pacc + p_lo * Hh;
        float* ahi = g_pacc + p_hi * Hh;
#pragma unroll
        for (int nt = 0; nt < 8; ++nt) {
            int col = nt * 8 + 2 * fc;
            *reinterpret_cast<float2*>(alo + col) = make_float2(o[nt][0], o[nt][1]);
            *reinterpret_cast<float2*>(ahi + col) = make_float2(o[nt][2], o[nt][3]);
        }
    }
}

// ============================================================
// Kernel 3: merge splits.
// ============================================================
__global__ __launch_bounds__(128) void attn_reduce_kernel(float* __restrict__ out)
{
    const int tid = threadIdx.x;
    const size_t qq = (size_t)blockIdx.x * 2 + (tid >> 6);
    const int h = tid & 63;

    float m_tot = -1e30f;
#pragma unroll
    for (int s = 0; s < NSPLIT; ++s)
        m_tot = fmaxf(m_tot, g_pm[qq * NSPLIT + s]);

    float num = 0.f, den = 0.f;
#pragma unroll
    for (int s = 0; s < NSPLIT; ++s) {
        float w = __expf(g_pm[qq * NSPLIT + s] - m_tot);
        den += w * g_pl[qq * NSPLIT + s];
        num += w * g_pacc[(qq * NSPLIT + s) * Hh + h];
    }
    out[qq * Hh + h] = num / den;
}

// ============================================================
extern "C" void kernel_launch(void* const* d_in, const int* in_sizes, int n_in,
                              void* d_out, int out_size)
{
    const float* x  = (const float*)d_in[0];
    const float* Wq = (const float*)d_in[1];
    const float* Wk = (const float*)d_in[2];
    const float* Wv = (const float*)d_in[3];
    float* out = (float*)d_out;

    dim3 pgrid(Bb * Tt / 64, 3);
    proj_mma_kernel<<<pgrid, 128>>>(x, Wq, Wk, Wv);

    dim3 agrid(Tt / BM, NSPLIT, Bb);
    attn_mma_kernel<<<agrid, 256>>>();

    attn_reduce_kernel<<<Bb * Tt / 2, 128>>>(out);
}

// round 6
// speedup vs baseline: 4.1630x; 1.1381x over previous
#include <cuda_runtime.h>
#include <math.h>
#include <stdint.h>

#define Bb 4
#define Tt 4096
#define Cc 1024
#define Hh 64
#define BM 128      // queries per attention CTA
#define KT 32       // keys per inner tile
#define NSPLIT 8
#define SCALE 0.03125f   // C^-0.5 = 1/32

// ---- scratch (no cudaMalloc allowed) ----
__device__ float g_q[Bb*Tt*Hh];
__device__ float g_k[Bb*Tt*Hh];
__device__ float g_v[Bb*Tt*Hh];
__device__ float g_pm[Bb*Tt*NSPLIT];
__device__ float g_pl[Bb*Tt*NSPLIT];
__device__ float g_pacc[(size_t)Bb*Tt*NSPLIT*Hh];

__device__ __forceinline__ float tf32r(float x) {  // round-to-nearest tf32
    uint32_t u;
    asm("cvt.rna.tf32.f32 %0, %1;" : "=r"(u) : "f"(x));
    return __uint_as_float(u);
}

__device__ __forceinline__ void mma_tf32(float* d, const uint32_t* a, uint32_t b0, uint32_t b1) {
    asm volatile(
        "mma.sync.aligned.m16n8k8.row.col.f32.tf32.tf32.f32 "
        "{%0,%1,%2,%3}, {%4,%5,%6,%7}, {%8,%9}, {%0,%1,%2,%3};"
        : "+f"(d[0]), "+f"(d[1]), "+f"(d[2]), "+f"(d[3])
        : "r"(a[0]), "r"(a[1]), "r"(a[2]), "r"(a[3]), "r"(b0), "r"(b1));
}

// ============================================================
// Kernel 1: QKV projection via mma.sync tf32 (hi/lo split on A).
// mt=2: each warp owns 32 rows -> B-fragment reuse x2.
// CTA: 128 threads (4 warps), M-tile 128, N=64, K-chunk 32.
// grid: (BT/128, 3).
// ============================================================
#define AS_STRIDE 36
#define BS_STRIDE 72

__global__ __launch_bounds__(128) void proj_mma_kernel(
    const float* __restrict__ x,
    const float* __restrict__ Wq,
    const float* __restrict__ Wk,
    const float* __restrict__ Wv)
{
    __shared__ float As_hi[128][AS_STRIDE];
    __shared__ float As_lo[128][AS_STRIDE];
    __shared__ float Bs[32][BS_STRIDE];

    const float* W;
    float* out;
    if (blockIdx.y == 0)      { W = Wq; out = g_q; }
    else if (blockIdx.y == 1) { W = Wk; out = g_k; }
    else                      { W = Wv; out = g_v; }

    const int row0 = blockIdx.x * 128;
    const int tid = threadIdx.x;
    const int wid = tid >> 5, lid = tid & 31;
    const int m0 = wid * 32;
    const int fr = lid >> 2;     // fragment row 0..7
    const int fc = lid & 3;      // fragment col 0..3

    float acc[2][8][4];
#pragma unroll
    for (int mt = 0; mt < 2; ++mt)
#pragma unroll
        for (int nt = 0; nt < 8; ++nt)
#pragma unroll
            for (int u = 0; u < 4; ++u) acc[mt][nt][u] = 0.f;

    for (int kc = 0; kc < Cc / 32; ++kc) {
        const int k0c = kc * 32;
        // --- A tile: 128 rows x 32 k, hi/lo split ---
#pragma unroll
        for (int r = 0; r < 8; ++r) {
            int f = tid + r * 128;
            int m = f >> 3, c4 = f & 7;
            float4 a = *reinterpret_cast<const float4*>(x + (size_t)(row0 + m) * Cc + k0c + c4 * 4);
            float hx = tf32r(a.x), hy = tf32r(a.y), hz = tf32r(a.z), hw = tf32r(a.w);
            As_hi[m][c4 * 4 + 0] = hx;  As_lo[m][c4 * 4 + 0] = tf32r(a.x - hx);
            As_hi[m][c4 * 4 + 1] = hy;  As_lo[m][c4 * 4 + 1] = tf32r(a.y - hy);
            As_hi[m][c4 * 4 + 2] = hz;  As_lo[m][c4 * 4 + 2] = tf32r(a.z - hz);
            As_hi[m][c4 * 4 + 3] = hw;  As_lo[m][c4 * 4 + 3] = tf32r(a.w - hw);
        }
        // --- B tile: 32 k x 64 n ---
#pragma unroll
        for (int r = 0; r < 4; ++r) {
            int f = tid + r * 128;
            int kk = f >> 4, c4 = f & 15;
            float4 w4 = *reinterpret_cast<const float4*>(W + (size_t)(k0c + kk) * Hh + c4 * 4);
            Bs[kk][c4 * 4 + 0] = tf32r(w4.x);
            Bs[kk][c4 * 4 + 1] = tf32r(w4.y);
            Bs[kk][c4 * 4 + 2] = tf32r(w4.z);
            Bs[kk][c4 * 4 + 3] = tf32r(w4.w);
        }
        __syncthreads();

#pragma unroll
        for (int ks = 0; ks < 4; ++ks) {
            const int k0 = ks * 8;
            uint32_t ahi[2][4], alo[2][4];
#pragma unroll
            for (int mt = 0; mt < 2; ++mt) {
                const int mb = m0 + mt * 16;
                ahi[mt][0] = __float_as_uint(As_hi[mb + fr    ][k0 + fc    ]);
                ahi[mt][1] = __float_as_uint(As_hi[mb + fr + 8][k0 + fc    ]);
                ahi[mt][2] = __float_as_uint(As_hi[mb + fr    ][k0 + fc + 4]);
                ahi[mt][3] = __float_as_uint(As_hi[mb + fr + 8][k0 + fc + 4]);
                alo[mt][0] = __float_as_uint(As_lo[mb + fr    ][k0 + fc    ]);
                alo[mt][1] = __float_as_uint(As_lo[mb + fr + 8][k0 + fc    ]);
                alo[mt][2] = __float_as_uint(As_lo[mb + fr    ][k0 + fc + 4]);
                alo[mt][3] = __float_as_uint(As_lo[mb + fr + 8][k0 + fc + 4]);
            }
#pragma unroll
            for (int nt = 0; nt < 8; ++nt) {
                uint32_t b0 = __float_as_uint(Bs[k0 + fc    ][nt * 8 + fr]);
                uint32_t b1 = __float_as_uint(Bs[k0 + fc + 4][nt * 8 + fr]);
#pragma unroll
                for (int mt = 0; mt < 2; ++mt) {
                    mma_tf32(acc[mt][nt], ahi[mt], b0, b1);
                    mma_tf32(acc[mt][nt], alo[mt], b0, b1);
                }
            }
        }
        __syncthreads();
    }

#pragma unroll
    for (int mt = 0; mt < 2; ++mt) {
        float* obase = out + (size_t)(row0 + m0 + mt * 16) * Hh;
#pragma unroll
        for (int nt = 0; nt < 8; ++nt) {
            int col = nt * 8 + 2 * fc;
            *reinterpret_cast<float2*>(obase + (size_t)fr * Hh + col)       = make_float2(acc[mt][nt][0], acc[mt][nt][1]);
            *reinterpret_cast<float2*>(obase + (size_t)(fr + 8) * Hh + col) = make_float2(acc[mt][nt][2], acc[mt][nt][3]);
        }
    }
}

// ============================================================
// Kernel 2: flash attention partials via mma.sync tf32.
// S^T = K @ Q^T  (A=K natural layout, B=Q frags in registers),
// softmax state per-column, P round-trip through smem, O = P@V.
// grid (T/BM, NSPLIT, B), 256 threads (8 warps, 16 q-rows each).
// ============================================================
#define PS_S 36
#define KS_S 68
#define VS_S 72

__global__ __launch_bounds__(256) void attn_mma_kernel()
{
    __shared__ float Ps[BM * PS_S];      // Q staging, then P tile
    __shared__ float Ks[KT * KS_S];
    __shared__ float Vs[KT * VS_S];
    __shared__ float s_corr[BM];

    const int qt = (Tt / BM - 1) - blockIdx.x;   // big tiles first
    const int sp = blockIdx.y;
    const int b  = blockIdx.z;
    const int q0 = qt * BM;
    const int tid = threadIdx.x, wid = tid >> 5, lid = tid & 31;
    const int fr = lid >> 2, fc = lid & 3;
    const int m0 = wid * 16;

    const int n_kt = (qt + 1) * (BM / KT);
    const int per = (n_kt + NSPLIT - 1) / NSPLIT;
    const int kt0 = sp * per;
    const int kt1 = min(kt0 + per, n_kt);

    if (kt0 >= kt1) {   // empty split: zero partials
        int q = tid >> 1, half = tid & 1;
        size_t pidx = ((size_t)b * Tt + q0 + q) * NSPLIT + sp;
        if (half == 0) { g_pm[pidx] = -1e30f; g_pl[pidx] = 0.f; }
        float4 z = make_float4(0.f, 0.f, 0.f, 0.f);
        float4* pa = reinterpret_cast<float4*>(g_pacc + pidx * Hh) + half * 8;
#pragma unroll
        for (int i2 = 0; i2 < 8; ++i2) pa[i2] = z;
        return;
    }

    // ---- stage Q, hoist B-fragments to registers (two h-halves) ----
    uint32_t qf[8][2][2];   // [k-step][n-subtile][b0/b1]
#pragma unroll
    for (int half = 0; half < 2; ++half) {
#pragma unroll
        for (int r = 0; r < 4; ++r) {
            int idx = tid + r * 256;
            int q = idx >> 3, h4 = idx & 7;
            float4 v = *reinterpret_cast<const float4*>(
                g_q + ((size_t)b * Tt + q0 + q) * Hh + half * 32 + h4 * 4);
            float* d = &Ps[q * PS_S + h4 * 4];
            d[0] = tf32r(v.x); d[1] = tf32r(v.y); d[2] = tf32r(v.z); d[3] = tf32r(v.w);
        }
        __syncthreads();
#pragma unroll
        for (int ks = 0; ks < 4; ++ks)
#pragma unroll
            for (int nt = 0; nt < 2; ++nt) {
                qf[half * 4 + ks][nt][0] = __float_as_uint(Ps[(m0 + 8 * nt + fr) * PS_S + ks * 8 + fc]);
                qf[half * 4 + ks][nt][1] = __float_as_uint(Ps[(m0 + 8 * nt + fr) * PS_S + ks * 8 + fc + 4]);
            }
        __syncthreads();
    }

    float o[8][4];
#pragma unroll
    for (int nt = 0; nt < 8; ++nt)
#pragma unroll
        for (int u = 0; u < 4; ++u) o[nt][u] = 0.f;
    float m_run[2][2], l_run[2][2];
#pragma unroll
    for (int a = 0; a < 2; ++a)
#pragma unroll
        for (int c = 0; c < 2; ++c) { m_run[a][c] = -1e30f; l_run[a][c] = 0.f; }

    for (int kt = kt0; kt < kt1; ++kt) {
        const int jb = kt * KT;
        // ---- load K, V tiles (tf32-rounded) ----
#pragma unroll
        for (int r = 0; r < 2; ++r) {
            int idx = tid + r * 256;
            int key = idx >> 4, h4 = idx & 15;
            size_t gidx = ((size_t)b * Tt + jb + key) * Hh + h4 * 4;
            float4 kv = *reinterpret_cast<const float4*>(g_k + gidx);
            float* dk = &Ks[key * KS_S + h4 * 4];
            dk[0] = tf32r(kv.x); dk[1] = tf32r(kv.y); dk[2] = tf32r(kv.z); dk[3] = tf32r(kv.w);
            float4 vv = *reinterpret_cast<const float4*>(g_v + gidx);
            float* dv = &Vs[key * VS_S + h4 * 4];
            dv[0] = tf32r(vv.x); dv[1] = tf32r(vv.y); dv[2] = tf32r(vv.z); dv[3] = tf32r(vv.w);
        }
        __syncthreads();

        // ---- S^T = K @ Q^T : [32 keys][16 q] per warp ----
        float sacc[2][2][4];
#pragma unroll
        for (int mt = 0; mt < 2; ++mt)
#pragma unroll
            for (int nt = 0; nt < 2; ++nt)
#pragma unroll
                for (int u = 0; u < 4; ++u) sacc[mt][nt][u] = 0.f;
#pragma unroll
        for (int ks = 0; ks < 8; ++ks) {
            uint32_t ak[2][4];
#pragma unroll
            for (int mt = 0; mt < 2; ++mt) {
                ak[mt][0] = __float_as_uint(Ks[(16 * mt + fr    ) * KS_S + ks * 8 + fc    ]);
                ak[mt][1] = __float_as_uint(Ks[(16 * mt + fr + 8) * KS_S + ks * 8 + fc    ]);
                ak[mt][2] = __float_as_uint(Ks[(16 * mt + fr    ) * KS_S + ks * 8 + fc + 4]);
                ak[mt][3] = __float_as_uint(Ks[(16 * mt + fr + 8) * KS_S + ks * 8 + fc + 4]);
            }
#pragma unroll
            for (int mt = 0; mt < 2; ++mt)
#pragma unroll
                for (int nt = 0; nt < 2; ++nt)
                    mma_tf32(sacc[mt][nt], ak[mt], qf[ks][nt][0], qf[ks][nt][1]);
        }

        // ---- per-column online softmax ----
#pragma unroll
        for (int nt = 0; nt < 2; ++nt)
#pragma unroll
        for (int cp = 0; cp < 2; ++cp) {
            const int qloc = m0 + 8 * nt + 2 * fc + cp;
            const int qg = q0 + qloc;
            float sv[4];
#pragma unroll
            for (int mt = 0; mt < 2; ++mt)
#pragma unroll
                for (int s2 = 0; s2 < 2; ++s2) {
                    int keyg = jb + 16 * mt + 8 * s2 + fr;
                    float v = sacc[mt][nt][s2 * 2 + cp] * SCALE;
                    sv[mt * 2 + s2] = (keyg <= qg) ? v : -1e30f;
                }
            float cm = fmaxf(fmaxf(sv[0], sv[1]), fmaxf(sv[2], sv[3]));
            cm = fmaxf(cm, __shfl_xor_sync(0xffffffffu, cm, 4));
            cm = fmaxf(cm, __shfl_xor_sync(0xffffffffu, cm, 8));
            cm = fmaxf(cm, __shfl_xor_sync(0xffffffffu, cm, 16));
            float mn = fmaxf(m_run[nt][cp], cm);
            float corr = __expf(m_run[nt][cp] - mn);
            m_run[nt][cp] = mn;
            float tl = 0.f;
#pragma unroll
            for (int u = 0; u < 4; ++u) { sv[u] = __expf(sv[u] - mn); tl += sv[u]; }
            tl += __shfl_xor_sync(0xffffffffu, tl, 4);
            tl += __shfl_xor_sync(0xffffffffu, tl, 8);
            tl += __shfl_xor_sync(0xffffffffu, tl, 16);
            l_run[nt][cp] = l_run[nt][cp] * corr + tl;
#pragma unroll
            for (int mt = 0; mt < 2; ++mt)
#pragma unroll
                for (int s2 = 0; s2 < 2; ++s2)
                    Ps[qloc * PS_S + 16 * mt + 8 * s2 + fr] = tf32r(sv[mt * 2 + s2]);
            if (fr == 0) s_corr[qloc] = corr;
        }
        __syncwarp();

        // ---- rescale O, then O += P @ V ----
        float clo = s_corr[m0 + fr], chi = s_corr[m0 + fr + 8];
#pragma unroll
        for (int nt = 0; nt < 8; ++nt) {
            o[nt][0] *= clo; o[nt][1] *= clo;
            o[nt][2] *= chi; o[nt][3] *= chi;
        }
#pragma unroll
        for (int ks = 0; ks < 4; ++ks) {
            uint32_t ap[4];
            ap[0] = __float_as_uint(Ps[(m0 + fr    ) * PS_S + ks * 8 + fc    ]);
            ap[1] = __float_as_uint(Ps[(m0 + fr + 8) * PS_S + ks * 8 + fc    ]);
            ap[2] = __float_as_uint(Ps[(m0 + fr    ) * PS_S + ks * 8 + fc + 4]);
            ap[3] = __float_as_uint(Ps[(m0 + fr + 8) * PS_S + ks * 8 + fc + 4]);
#pragma unroll
            for (int nt = 0; nt < 8; ++nt) {
                uint32_t b0 = __float_as_uint(Vs[(ks * 8 + fc    ) * VS_S + nt * 8 + fr]);
                uint32_t b1 = __float_as_uint(Vs[(ks * 8 + fc + 4) * VS_S + nt * 8 + fr]);
                mma_tf32(o[nt], ap, b0, b1);
            }
        }
        __syncthreads();
    }

    // ---- store partials ----
    if (fr == 0) {
#pragma unroll
        for (int nt = 0; nt < 2; ++nt)
#pragma unroll
            for (int cp = 0; cp < 2; ++cp) {
                int qloc = m0 + 8 * nt + 2 * fc + cp;
                size_t pidx = ((size_t)b * Tt + q0 + qloc) * NSPLIT + sp;
                g_pm[pidx] = m_run[nt][cp];
                g_pl[pidx] = l_run[nt][cp];
            }
    }
    {
        size_t p_lo = ((size_t)b * Tt + q0 + m0 + fr    ) * NSPLIT + sp;
        size_t p_hi = ((size_t)b * Tt + q0 + m0 + fr + 8) * NSPLIT + sp;
        float* alo = g_pacc + p_lo * Hh;
        float* ahi = g_pacc + p_hi * Hh;
#pragma unroll
        for (int nt = 0; nt < 8; ++nt) {
            int col = nt * 8 + 2 * fc;
            *reinterpret_cast<float2*>(alo + col) = make_float2(o[nt][0], o[nt][1]);
            *reinterpret_cast<float2*>(ahi + col) = make_float2(o[nt][2], o[nt][3]);
        }
    }
}

// ============================================================
// Kernel 3: merge splits.
// ============================================================
__global__ __launch_bounds__(128) void attn_reduce_kernel(float* __restrict__ out)
{
    const int tid = threadIdx.x;
    const size_t qq = (size_t)blockIdx.x * 2 + (tid >> 6);
    const int h = tid & 63;

    float m_tot = -1e30f;
#pragma unroll
    for (int s = 0; s < NSPLIT; ++s)
        m_tot = fmaxf(m_tot, g_pm[qq * NSPLIT + s]);

    float num = 0.f, den = 0.f;
#pragma unroll
    for (int s = 0; s < NSPLIT; ++s) {
        float w = __expf(g_pm[qq * NSPLIT + s] - m_tot);
        den += w * g_pl[qq * NSPLIT + s];
        num += w * g_pacc[(qq * NSPLIT + s) * Hh + h];
    }
    out[qq * Hh + h] = num / den;
}

// ============================================================
extern "C" void kernel_launch(void* const* d_in, const int* in_sizes, int n_in,
                              void* d_out, int out_size)
{
    const float* x  = (const float*)d_in[0];
    const float* Wq = (const float*)d_in[1];
    const float* Wk = (const float*)d_in[2];
    const float* Wv = (const float*)d_in[3];
    float* out = (float*)d_out;

    dim3 pgrid(Bb * Tt / 128, 3);
    proj_mma_kernel<<<pgrid, 128>>>(x, Wq, Wk, Wv);

    dim3 agrid(Tt / BM, NSPLIT, Bb);
    attn_mma_kernel<<<agrid, 256>>>();

    attn_reduce_kernel<<<Bb * Tt / 2, 128>>>(out);
}

// round 7
// speedup vs baseline: 5.2360x; 1.2577x over previous
#include <cuda_runtime.h>
#include <math.h>
#include <stdint.h>

#define Bb 4
#define Tt 4096
#define Cc 1024
#define Hh 64
#define BM 128      // queries per attention CTA
#define KT 32       // keys per inner tile
#define NSPLIT 8
#define SCALE 0.03125f   // C^-0.5 = 1/32

// ---- scratch (no cudaMalloc allowed) ----
__device__ float g_q[Bb*Tt*Hh];
__device__ float g_k[Bb*Tt*Hh];
__device__ float g_v[Bb*Tt*Hh];
__device__ float g_pm[Bb*Tt*NSPLIT];
__device__ float g_pl[Bb*Tt*NSPLIT];
__device__ float g_pacc[(size_t)Bb*Tt*NSPLIT*Hh];

__device__ __forceinline__ float tf32r(float x) {  // round-to-nearest tf32
    uint32_t u;
    asm("cvt.rna.tf32.f32 %0, %1;" : "=r"(u) : "f"(x));
    return __uint_as_float(u);
}

__device__ __forceinline__ void mma_tf32(float* d, const uint32_t* a, uint32_t b0, uint32_t b1) {
    asm volatile(
        "mma.sync.aligned.m16n8k8.row.col.f32.tf32.tf32.f32 "
        "{%0,%1,%2,%3}, {%4,%5,%6,%7}, {%8,%9}, {%0,%1,%2,%3};"
        : "+f"(d[0]), "+f"(d[1]), "+f"(d[2]), "+f"(d[3])
        : "r"(a[0]), "r"(a[1]), "r"(a[2]), "r"(a[3]), "r"(b0), "r"(b1));
}

// ============================================================
// Kernel 1: FUSED QKV projection, single-pass tf32.
// A tile (x) staged once, feeds all 3 weight matrices (N=192).
// 256 threads (8 warps x 16 rows), M-tile 128, K-chunk 32.
// grid: BT/128 = 128 CTAs.
// ============================================================
#define AS_STRIDE 36
#define BS3 200          // 192 cols + 8 pad

__global__ __launch_bounds__(256) void proj_fused_kernel(
    const float* __restrict__ x,
    const float* __restrict__ Wq,
    const float* __restrict__ Wk,
    const float* __restrict__ Wv)
{
    __shared__ float As[128][AS_STRIDE];
    __shared__ float Bs[32][BS3];

    const int row0 = blockIdx.x * 128;
    const int tid = threadIdx.x;
    const int wid = tid >> 5, lid = tid & 31;
    const int m0 = wid * 16;
    const int fr = lid >> 2;     // fragment row 0..7
    const int fc = lid & 3;      // fragment col 0..3

    float acc[24][4];
#pragma unroll
    for (int nt = 0; nt < 24; ++nt)
#pragma unroll
        for (int u = 0; u < 4; ++u) acc[nt][u] = 0.f;

    for (int kc = 0; kc < Cc / 32; ++kc) {
        const int k0c = kc * 32;
        // --- A tile: 128 rows x 32 k, tf32-rounded ---
#pragma unroll
        for (int r = 0; r < 4; ++r) {
            int f = tid + r * 256;
            int m = f >> 3, c4 = f & 7;
            float4 a = *reinterpret_cast<const float4*>(x + (size_t)(row0 + m) * Cc + k0c + c4 * 4);
            As[m][c4 * 4 + 0] = tf32r(a.x);
            As[m][c4 * 4 + 1] = tf32r(a.y);
            As[m][c4 * 4 + 2] = tf32r(a.z);
            As[m][c4 * 4 + 3] = tf32r(a.w);
        }
        // --- B tile: 32 k x 192 n  (Wq | Wk | Wv) ---
#pragma unroll
        for (int mat = 0; mat < 3; ++mat) {
            const float* W = (mat == 0) ? Wq : (mat == 1) ? Wk : Wv;
#pragma unroll
            for (int r = 0; r < 2; ++r) {
                int f = tid + r * 256;
                int kk = f >> 4, c4 = f & 15;
                float4 w4 = *reinterpret_cast<const float4*>(W + (size_t)(k0c + kk) * Hh + c4 * 4);
                float* d = &Bs[kk][mat * 64 + c4 * 4];
                d[0] = tf32r(w4.x); d[1] = tf32r(w4.y); d[2] = tf32r(w4.z); d[3] = tf32r(w4.w);
            }
        }
        __syncthreads();

#pragma unroll
        for (int ks = 0; ks < 4; ++ks) {
            const int k0 = ks * 8;
            uint32_t af[4];
            af[0] = __float_as_uint(As[m0 + fr    ][k0 + fc    ]);
            af[1] = __float_as_uint(As[m0 + fr + 8][k0 + fc    ]);
            af[2] = __float_as_uint(As[m0 + fr    ][k0 + fc + 4]);
            af[3] = __float_as_uint(As[m0 + fr + 8][k0 + fc + 4]);
#pragma unroll
            for (int nt = 0; nt < 24; ++nt) {
                uint32_t b0 = __float_as_uint(Bs[k0 + fc    ][nt * 8 + fr]);
                uint32_t b1 = __float_as_uint(Bs[k0 + fc + 4][nt * 8 + fr]);
                mma_tf32(acc[nt], af, b0, b1);
            }
        }
        __syncthreads();
    }

    // epilogue: 3 output matrices
#pragma unroll
    for (int mat = 0; mat < 3; ++mat) {
        float* out = (mat == 0) ? g_q : (mat == 1) ? g_k : g_v;
        float* obase = out + (size_t)(row0 + m0) * Hh;
#pragma unroll
        for (int j = 0; j < 8; ++j) {
            int nt = mat * 8 + j;
            int col = j * 8 + 2 * fc;
            *reinterpret_cast<float2*>(obase + (size_t)fr * Hh + col)       = make_float2(acc[nt][0], acc[nt][1]);
            *reinterpret_cast<float2*>(obase + (size_t)(fr + 8) * Hh + col) = make_float2(acc[nt][2], acc[nt][3]);
        }
    }
}

// ============================================================
// Kernel 2: flash attention partials via mma.sync tf32 (unchanged).
// ============================================================
#define PS_S 36
#define KS_S 68
#define VS_S 72

__global__ __launch_bounds__(256) void attn_mma_kernel()
{
    __shared__ float Ps[BM * PS_S];      // Q staging, then P tile
    __shared__ float Ks[KT * KS_S];
    __shared__ float Vs[KT * VS_S];
    __shared__ float s_corr[BM];

    const int qt = (Tt / BM - 1) - blockIdx.x;   // big tiles first
    const int sp = blockIdx.y;
    const int b  = blockIdx.z;
    const int q0 = qt * BM;
    const int tid = threadIdx.x, wid = tid >> 5, lid = tid & 31;
    const int fr = lid >> 2, fc = lid & 3;
    const int m0 = wid * 16;

    const int n_kt = (qt + 1) * (BM / KT);
    const int per = (n_kt + NSPLIT - 1) / NSPLIT;
    const int kt0 = sp * per;
    const int kt1 = min(kt0 + per, n_kt);

    if (kt0 >= kt1) {   // empty split: zero partials
        int q = tid >> 1, half = tid & 1;
        size_t pidx = ((size_t)b * Tt + q0 + q) * NSPLIT + sp;
        if (half == 0) { g_pm[pidx] = -1e30f; g_pl[pidx] = 0.f; }
        float4 z = make_float4(0.f, 0.f, 0.f, 0.f);
        float4* pa = reinterpret_cast<float4*>(g_pacc + pidx * Hh) + half * 8;
#pragma unroll
        for (int i2 = 0; i2 < 8; ++i2) pa[i2] = z;
        return;
    }

    // ---- stage Q, hoist B-fragments to registers (two h-halves) ----
    uint32_t qf[8][2][2];   // [k-step][n-subtile][b0/b1]
#pragma unroll
    for (int half = 0; half < 2; ++half) {
#pragma unroll
        for (int r = 0; r < 4; ++r) {
            int idx = tid + r * 256;
            int q = idx >> 3, h4 = idx & 7;
            float4 v = *reinterpret_cast<const float4*>(
                g_q + ((size_t)b * Tt + q0 + q) * Hh + half * 32 + h4 * 4);
            float* d = &Ps[q * PS_S + h4 * 4];
            d[0] = tf32r(v.x); d[1] = tf32r(v.y); d[2] = tf32r(v.z); d[3] = tf32r(v.w);
        }
        __syncthreads();
#pragma unroll
        for (int ks = 0; ks < 4; ++ks)
#pragma unroll
            for (int nt = 0; nt < 2; ++nt) {
                qf[half * 4 + ks][nt][0] = __float_as_uint(Ps[(m0 + 8 * nt + fr) * PS_S + ks * 8 + fc]);
                qf[half * 4 + ks][nt][1] = __float_as_uint(Ps[(m0 + 8 * nt + fr) * PS_S + ks * 8 + fc + 4]);
            }
        __syncthreads();
    }

    float o[8][4];
#pragma unroll
    for (int nt = 0; nt < 8; ++nt)
#pragma unroll
        for (int u = 0; u < 4; ++u) o[nt][u] = 0.f;
    float m_run[2][2], l_run[2][2];
#pragma unroll
    for (int a = 0; a < 2; ++a)
#pragma unroll
        for (int c = 0; c < 2; ++c) { m_run[a][c] = -1e30f; l_run[a][c] = 0.f; }

    for (int kt = kt0; kt < kt1; ++kt) {
        const int jb = kt * KT;
        // ---- load K, V tiles (tf32-rounded) ----
#pragma unroll
        for (int r = 0; r < 2; ++r) {
            int idx = tid + r * 256;
            int key = idx >> 4, h4 = idx & 15;
            size_t gidx = ((size_t)b * Tt + jb + key) * Hh + h4 * 4;
            float4 kv = *reinterpret_cast<const float4*>(g_k + gidx);
            float* dk = &Ks[key * KS_S + h4 * 4];
            dk[0] = tf32r(kv.x); dk[1] = tf32r(kv.y); dk[2] = tf32r(kv.z); dk[3] = tf32r(kv.w);
            float4 vv = *reinterpret_cast<const float4*>(g_v + gidx);
            float* dv = &Vs[key * VS_S + h4 * 4];
            dv[0] = tf32r(vv.x); dv[1] = tf32r(vv.y); dv[2] = tf32r(vv.z); dv[3] = tf32r(vv.w);
        }
        __syncthreads();

        // ---- S^T = K @ Q^T : [32 keys][16 q] per warp ----
        float sacc[2][2][4];
#pragma unroll
        for (int mt = 0; mt < 2; ++mt)
#pragma unroll
            for (int nt = 0; nt < 2; ++nt)
#pragma unroll
                for (int u = 0; u < 4; ++u) sacc[mt][nt][u] = 0.f;
#pragma unroll
        for (int ks = 0; ks < 8; ++ks) {
            uint32_t ak[2][4];
#pragma unroll
            for (int mt = 0; mt < 2; ++mt) {
                ak[mt][0] = __float_as_uint(Ks[(16 * mt + fr    ) * KS_S + ks * 8 + fc    ]);
                ak[mt][1] = __float_as_uint(Ks[(16 * mt + fr + 8) * KS_S + ks * 8 + fc    ]);
                ak[mt][2] = __float_as_uint(Ks[(16 * mt + fr    ) * KS_S + ks * 8 + fc + 4]);
                ak[mt][3] = __float_as_uint(Ks[(16 * mt + fr + 8) * KS_S + ks * 8 + fc + 4]);
            }
#pragma unroll
            for (int mt = 0; mt < 2; ++mt)
#pragma unroll
                for (int nt = 0; nt < 2; ++nt)
                    mma_tf32(sacc[mt][nt], ak[mt], qf[ks][nt][0], qf[ks][nt][1]);
        }

        // ---- per-column online softmax ----
#pragma unroll
        for (int nt = 0; nt < 2; ++nt)
#pragma unroll
        for (int cp = 0; cp < 2; ++cp) {
            const int qloc = m0 + 8 * nt + 2 * fc + cp;
            const int qg = q0 + qloc;
            float sv[4];
#pragma unroll
            for (int mt = 0; mt < 2; ++mt)
#pragma unroll
                for (int s2 = 0; s2 < 2; ++s2) {
                    int keyg = jb + 16 * mt + 8 * s2 + fr;
                    float v = sacc[mt][nt][s2 * 2 + cp] * SCALE;
                    sv[mt * 2 + s2] = (keyg <= qg) ? v : -1e30f;
                }
            float cm = fmaxf(fmaxf(sv[0], sv[1]), fmaxf(sv[2], sv[3]));
            cm = fmaxf(cm, __shfl_xor_sync(0xffffffffu, cm, 4));
            cm = fmaxf(cm, __shfl_xor_sync(0xffffffffu, cm, 8));
            cm = fmaxf(cm, __shfl_xor_sync(0xffffffffu, cm, 16));
            float mn = fmaxf(m_run[nt][cp], cm);
            float corr = __expf(m_run[nt][cp] - mn);
            m_run[nt][cp] = mn;
            float tl = 0.f;
#pragma unroll
            for (int u = 0; u < 4; ++u) { sv[u] = __expf(sv[u] - mn); tl += sv[u]; }
            tl += __shfl_xor_sync(0xffffffffu, tl, 4);
            tl += __shfl_xor_sync(0xffffffffu, tl, 8);
            tl += __shfl_xor_sync(0xffffffffu, tl, 16);
            l_run[nt][cp] = l_run[nt][cp] * corr + tl;
#pragma unroll
            for (int mt = 0; mt < 2; ++mt)
#pragma unroll
                for (int s2 = 0; s2 < 2; ++s2)
                    Ps[qloc * PS_S + 16 * mt + 8 * s2 + fr] = tf32r(sv[mt * 2 + s2]);
            if (fr == 0) s_corr[qloc] = corr;
        }
        __syncwarp();

        // ---- rescale O, then O += P @ V ----
        float clo = s_corr[m0 + fr], chi = s_corr[m0 + fr + 8];
#pragma unroll
        for (int nt = 0; nt < 8; ++nt) {
            o[nt][0] *= clo; o[nt][1] *= clo;
            o[nt][2] *= chi; o[nt][3] *= chi;
        }
#pragma unroll
        for (int ks = 0; ks < 4; ++ks) {
            uint32_t ap[4];
            ap[0] = __float_as_uint(Ps[(m0 + fr    ) * PS_S + ks * 8 + fc    ]);
            ap[1] = __float_as_uint(Ps[(m0 + fr + 8) * PS_S + ks * 8 + fc    ]);
            ap[2] = __float_as_uint(Ps[(m0 + fr    ) * PS_S + ks * 8 + fc + 4]);
            ap[3] = __float_as_uint(Ps[(m0 + fr + 8) * PS_S + ks * 8 + fc + 4]);
#pragma unroll
            for (int nt = 0; nt < 8; ++nt) {
                uint32_t b0 = __float_as_uint(Vs[(ks * 8 + fc    ) * VS_S + nt * 8 + fr]);
                uint32_t b1 = __float_as_uint(Vs[(ks * 8 + fc + 4) * VS_S + nt * 8 + fr]);
                mma_tf32(o[nt], ap, b0, b1);
            }
        }
        __syncthreads();
    }

    // ---- store partials ----
    if (fr == 0) {
#pragma unroll
        for (int nt = 0; nt < 2; ++nt)
#pragma unroll
            for (int cp = 0; cp < 2; ++cp) {
                int qloc = m0 + 8 * nt + 2 * fc + cp;
                size_t pidx = ((size_t)b * Tt + q0 + qloc) * NSPLIT + sp;
                g_pm[pidx] = m_run[nt][cp];
                g_pl[pidx] = l_run[nt][cp];
            }
    }
    {
        size_t p_lo = ((size_t)b * Tt + q0 + m0 + fr    ) * NSPLIT + sp;
        size_t p_hi = ((size_t)b * Tt + q0 + m0 + fr + 8) * NSPLIT + sp;
        float* alo = g_pacc + p_lo * Hh;
        float* ahi = g_pacc + p_hi * Hh;
#pragma unroll
        for (int nt = 0; nt < 8; ++nt) {
            int col = nt * 8 + 2 * fc;
            *reinterpret_cast<float2*>(alo + col) = make_float2(o[nt][0], o[nt][1]);
            *reinterpret_cast<float2*>(ahi + col) = make_float2(o[nt][2], o[nt][3]);
        }
    }
}

// ============================================================
// Kernel 3: merge splits (unchanged).
// ============================================================
__global__ __launch_bounds__(128) void attn_reduce_kernel(float* __restrict__ out)
{
    const int tid = threadIdx.x;
    const size_t qq = (size_t)blockIdx.x * 2 + (tid >> 6);
    const int h = tid & 63;

    float m_tot = -1e30f;
#pragma unroll
    for (int s = 0; s < NSPLIT; ++s)
        m_tot = fmaxf(m_tot, g_pm[qq * NSPLIT + s]);

    float num = 0.f, den = 0.f;
#pragma unroll
    for (int s = 0; s < NSPLIT; ++s) {
        float w = __expf(g_pm[qq * NSPLIT + s] - m_tot);
        den += w * g_pl[qq * NSPLIT + s];
        num += w * g_pacc[(qq * NSPLIT + s) * Hh + h];
    }
    out[qq * Hh + h] = num / den;
}

// ============================================================
extern "C" void kernel_launch(void* const* d_in, const int* in_sizes, int n_in,
                              void* d_out, int out_size)
{
    const float* x  = (const float*)d_in[0];
    const float* Wq = (const float*)d_in[1];
    const float* Wk = (const float*)d_in[2];
    const float* Wv = (const float*)d_in[3];
    float* out = (float*)d_out;

    proj_fused_kernel<<<Bb * Tt / 128, 256>>>(x, Wq, Wk, Wv);

    dim3 agrid(Tt / BM, NSPLIT, Bb);
    attn_mma_kernel<<<agrid, 256>>>();

    attn_reduce_kernel<<<Bb * Tt / 2, 128>>>(out);
}